// round 1
// baseline (speedup 1.0000x reference)
#include <cuda_runtime.h>

#define HH 64
#define NN 512
#define BB 128
#define NT 64     // n-rows per attention CTA
#define MT 128    // m-cols per K/V tile
#define SCALE 0.125f   // 1/sqrt(64)

// Scratch for projected q/k/v in [B, N, H] layout (16 MB each).
__device__ float g_qp[BB * NN * HH];
__device__ float g_kp[BB * NN * HH];
__device__ float g_vp[BB * NN * HH];

// ---------------------------------------------------------------------------
// Projection: dst[b,n,k] = sum_h x[n,b,h] * W[k,h] + bias[k]
// x is [N,B,H] row-major; rows of the flat GEMM are (n*B + b).
// One CTA = 64 flat rows x all 64 k. blockIdx.y selects q/k/v.
// ---------------------------------------------------------------------------
__global__ __launch_bounds__(256) void proj_kernel(
    const float* __restrict__ q, const float* __restrict__ k,
    const float* __restrict__ v,
    const float* __restrict__ Wq, const float* __restrict__ bq,
    const float* __restrict__ Wk, const float* __restrict__ bk,
    const float* __restrict__ Wv, const float* __restrict__ bv)
{
    __shared__ float sX[64][68];
    __shared__ float sW[64][68];
    __shared__ float sB[64];

    const float* x; const float* W; const float* bias; float* dst;
    if (blockIdx.y == 0)      { x = q; W = Wq; bias = bq; dst = g_qp; }
    else if (blockIdx.y == 1) { x = k; W = Wk; bias = bk; dst = g_kp; }
    else                      { x = v; W = Wv; bias = bv; dst = g_vp; }

    const int tid  = threadIdx.x;
    const int row0 = blockIdx.x * 64;

    // Load 64x64 X tile and 64x64 W into smem (float4, coalesced)
    #pragma unroll
    for (int it = 0; it < 4; it++) {
        int idx = tid + it * 256;         // float4 index, 0..1023
        int r = idx >> 4, c4 = idx & 15;
        float4 xv = reinterpret_cast<const float4*>(x + (size_t)(row0 + r) * HH)[c4];
        *reinterpret_cast<float4*>(&sX[r][c4 * 4]) = xv;
        float4 wv = reinterpret_cast<const float4*>(W + (size_t)r * HH)[c4];
        *reinterpret_cast<float4*>(&sW[r][c4 * 4]) = wv;
    }
    if (tid < 64) sB[tid] = bias[tid];
    __syncthreads();

    const int kk = tid & 15;   // k = kk + 16*i
    const int rg = tid >> 4;   // rows rg*4 + j

    float acc[4][4];
    #pragma unroll
    for (int j = 0; j < 4; j++)
        #pragma unroll
        for (int i = 0; i < 4; i++) acc[j][i] = 0.f;

    #pragma unroll
    for (int h = 0; h < HH; h += 4) {
        float4 xr[4], wr[4];
        #pragma unroll
        for (int j = 0; j < 4; j++)
            xr[j] = *reinterpret_cast<const float4*>(&sX[rg * 4 + j][h]);
        #pragma unroll
        for (int i = 0; i < 4; i++)
            wr[i] = *reinterpret_cast<const float4*>(&sW[kk + i * 16][h]);
        #pragma unroll
        for (int j = 0; j < 4; j++)
            #pragma unroll
            for (int i = 0; i < 4; i++)
                acc[j][i] += xr[j].x * wr[i].x + xr[j].y * wr[i].y
                           + xr[j].z * wr[i].z + xr[j].w * wr[i].w;
    }

    #pragma unroll
    for (int j = 0; j < 4; j++) {
        int grow = row0 + rg * 4 + j;
        int n = grow >> 7;       // / B  (B = 128)
        int b = grow & 127;      // % B
        float* orow = dst + ((size_t)b * NN + n) * HH;
        #pragma unroll
        for (int i = 0; i < 4; i++) {
            int kcol = kk + i * 16;
            orow[kcol] = acc[j][i] + sB[kcol];
        }
    }
}

// ---------------------------------------------------------------------------
// Attention: per (b, 64-row n-tile).
//   S = qp kp^T / 8 ; a = exp(S)*mask kept entirely in smem (64x512);
//   rowsum -> normalize once; write A and out.
// ---------------------------------------------------------------------------
__global__ __launch_bounds__(512, 1) void attn_kernel(
    const float* __restrict__ mask,
    float* __restrict__ out,     // [N,B,H]
    float* __restrict__ Aout)    // [B,N,N]
{
    extern __shared__ float sm[];
    float* sA   = sm;                    // 64*512
    float* sQ   = sA + 64 * 512;         // 64*68
    float* sK   = sQ + 64 * 68;          // 128*68
    float* sV   = sK + 128 * 68;         // 128*68
    float* sInv = sV + 128 * 68;         // 64

    const int tid = threadIdx.x;
    const int n0  = blockIdx.x * NT;
    const int b   = blockIdx.y;

    const float* qp = g_qp + (size_t)b * NN * HH;
    const float* kp = g_kp + (size_t)b * NN * HH;
    const float* vp = g_vp + (size_t)b * NN * HH;
    const float* mrow = mask + (size_t)b * NN * NN;

    // Load Q tile (64 x 64)
    #pragma unroll
    for (int it = 0; it < 2; it++) {
        int idx = tid + it * 512;
        int r = idx >> 4, c4 = idx & 15;
        float4 v4 = reinterpret_cast<const float4*>(qp + (size_t)(n0 + r) * HH)[c4];
        *reinterpret_cast<float4*>(&sQ[r * 68 + c4 * 4]) = v4;
    }

    // AV accumulator mapping: rows rA,rA+1 ; cols cA..cA+3
    const int rA = (tid >> 4) * 2;
    const int cA = (tid & 15) * 4;
    float acc[2][4] = {{0.f,0.f,0.f,0.f},{0.f,0.f,0.f,0.f}};

    // S mapping: cols cc + 32*i ; rows tr*4 + j
    const int cc = tid & 31;
    const int tr = tid >> 5;

    for (int mt = 0; mt < NN; mt += MT) {
        // Load K,V tiles (128 x 64 each)
        #pragma unroll
        for (int it = 0; it < 4; it++) {
            int idx = tid + it * 512;
            int r = idx >> 4, c4 = idx & 15;
            float4 kv = reinterpret_cast<const float4*>(kp + (size_t)(mt + r) * HH)[c4];
            *reinterpret_cast<float4*>(&sK[r * 68 + c4 * 4]) = kv;
            float4 vv = reinterpret_cast<const float4*>(vp + (size_t)(mt + r) * HH)[c4];
            *reinterpret_cast<float4*>(&sV[r * 68 + c4 * 4]) = vv;
        }
        __syncthreads();

        // S = Q K^T (64 x 128)
        float s[4][4];
        #pragma unroll
        for (int j = 0; j < 4; j++)
            #pragma unroll
            for (int i = 0; i < 4; i++) s[j][i] = 0.f;

        #pragma unroll
        for (int h = 0; h < HH; h += 4) {
            float4 qr[4], kr[4];
            #pragma unroll
            for (int j = 0; j < 4; j++)
                qr[j] = *reinterpret_cast<const float4*>(&sQ[(tr * 4 + j) * 68 + h]);
            #pragma unroll
            for (int i = 0; i < 4; i++)
                kr[i] = *reinterpret_cast<const float4*>(&sK[(cc + 32 * i) * 68 + h]);
            #pragma unroll
            for (int j = 0; j < 4; j++)
                #pragma unroll
                for (int i = 0; i < 4; i++)
                    s[j][i] += qr[j].x * kr[i].x + qr[j].y * kr[i].y
                             + qr[j].z * kr[i].z + qr[j].w * kr[i].w;
        }

        // exp(S/8) * mask -> sA
        #pragma unroll
        for (int j = 0; j < 4; j++) {
            int r = tr * 4 + j;
            const float* mr = mrow + (size_t)(n0 + r) * NN + mt;
            #pragma unroll
            for (int i = 0; i < 4; i++) {
                int c = cc + 32 * i;
                sA[r * 512 + mt + c] = __expf(s[j][i] * SCALE) * mr[c];
            }
        }
        __syncthreads();

        // acc += a_tile @ V_tile
        #pragma unroll 8
        for (int mm = 0; mm < MT; mm += 4) {
            float4 a0 = *reinterpret_cast<const float4*>(&sA[(size_t)rA * 512 + mt + mm]);
            float4 a1 = *reinterpret_cast<const float4*>(&sA[(size_t)(rA + 1) * 512 + mt + mm]);
            float4 v0 = *reinterpret_cast<const float4*>(&sV[(mm + 0) * 68 + cA]);
            float4 v1 = *reinterpret_cast<const float4*>(&sV[(mm + 1) * 68 + cA]);
            float4 v2 = *reinterpret_cast<const float4*>(&sV[(mm + 2) * 68 + cA]);
            float4 v3 = *reinterpret_cast<const float4*>(&sV[(mm + 3) * 68 + cA]);
            float am[2][4] = {{a0.x, a0.y, a0.z, a0.w}, {a1.x, a1.y, a1.z, a1.w}};
            float vm[4][4] = {{v0.x, v0.y, v0.z, v0.w}, {v1.x, v1.y, v1.z, v1.w},
                              {v2.x, v2.y, v2.z, v2.w}, {v3.x, v3.y, v3.z, v3.w}};
            #pragma unroll
            for (int j = 0; j < 2; j++)
                #pragma unroll
                for (int t = 0; t < 4; t++)
                    #pragma unroll
                    for (int i = 0; i < 4; i++)
                        acc[j][i] += am[j][t] * vm[t][i];
        }
        __syncthreads();
    }

    // Row sums: 8 threads/row, interleaved float4 chunks (conflict-free)
    {
        int rs_row = tid >> 3;
        int seg = tid & 7;
        float ssum = 0.f;
        #pragma unroll
        for (int it = 0; it < 16; it++) {
            float4 a = *reinterpret_cast<const float4*>(&sA[(size_t)rs_row * 512 + (seg + it * 8) * 4]);
            ssum += a.x + a.y + a.z + a.w;
        }
        ssum += __shfl_xor_sync(0xffffffff, ssum, 1);
        ssum += __shfl_xor_sync(0xffffffff, ssum, 2);
        ssum += __shfl_xor_sync(0xffffffff, ssum, 4);
        if (seg == 0) sInv[rs_row] = (ssum == 0.f) ? 1.f : (1.f / ssum);
    }
    __syncthreads();

    // Write normalized A (coalesced float4)
    float* Ab = Aout + (size_t)b * NN * NN;
    #pragma unroll
    for (int it = 0; it < 16; it++) {
        int idx = tid + it * 512;      // float4 idx over 64x128
        int r = idx >> 7, c4 = idx & 127;
        float4 a = *reinterpret_cast<const float4*>(&sA[(size_t)r * 512 + c4 * 4]);
        float inv = sInv[r];
        a.x *= inv; a.y *= inv; a.z *= inv; a.w *= inv;
        reinterpret_cast<float4*>(Ab + (size_t)(n0 + r) * NN)[c4] = a;
    }

    // Write out[n,b,h]
    #pragma unroll
    for (int j = 0; j < 2; j++) {
        int r = rA + j;
        float inv = sInv[r];
        float4 o;
        o.x = acc[j][0] * inv; o.y = acc[j][1] * inv;
        o.z = acc[j][2] * inv; o.w = acc[j][3] * inv;
        *reinterpret_cast<float4*>(out + ((size_t)(n0 + r) * BB + b) * HH + cA) = o;
    }
}

// ---------------------------------------------------------------------------
extern "C" void kernel_launch(void* const* d_in, const int* in_sizes, int n_in,
                              void* d_out, int out_size)
{
    const float* q    = (const float*)d_in[0];
    const float* k    = (const float*)d_in[1];
    const float* v    = (const float*)d_in[2];
    const float* mask = (const float*)d_in[3];
    const float* Wq   = (const float*)d_in[4];
    const float* bq   = (const float*)d_in[5];
    const float* Wk   = (const float*)d_in[6];
    const float* bk   = (const float*)d_in[7];
    const float* Wv   = (const float*)d_in[8];
    const float* bv   = (const float*)d_in[9];

    float* out  = (float*)d_out;                         // [N,B,H] first
    float* Aout = (float*)d_out + (size_t)NN * BB * HH;  // then [B,N,N]

    const int smem_bytes = (64 * 512 + 64 * 68 + 128 * 68 + 128 * 68 + 64) * 4;
    cudaFuncSetAttribute(attn_kernel, cudaFuncAttributeMaxDynamicSharedMemorySize,
                         smem_bytes);

    proj_kernel<<<dim3((NN * BB) / 64, 3), 256>>>(q, k, v, Wq, bq, Wk, bk, Wv, bv);
    attn_kernel<<<dim3(NN / NT, BB), 512, smem_bytes>>>(mask, out, Aout);
}

// round 3
// speedup vs baseline: 1.6651x; 1.6651x over previous
#include <cuda_runtime.h>
#include <cstdint>

#define HH 64
#define NN 512
#define BB 128
#define SCALE 0.125f

__device__ float g_qp[BB * NN * HH];
__device__ float g_kp[BB * NN * HH];
__device__ float g_vp[BB * NN * HH];

// ---------------- helpers ----------------
__device__ __forceinline__ uint32_t tf32r(float f) {
    uint32_t u;
    asm("cvt.rna.tf32.f32 %0, %1;" : "=r"(u) : "f"(f));
    return u;
}
__device__ __forceinline__ void mma_tf32(float* d, const uint32_t* a,
                                         uint32_t b0, uint32_t b1) {
    asm volatile(
        "mma.sync.aligned.m16n8k8.row.col.f32.tf32.tf32.f32 "
        "{%0,%1,%2,%3}, {%4,%5,%6,%7}, {%8,%9}, {%0,%1,%2,%3};"
        : "+f"(d[0]), "+f"(d[1]), "+f"(d[2]), "+f"(d[3])
        : "r"(a[0]), "r"(a[1]), "r"(a[2]), "r"(a[3]), "r"(b0), "r"(b1));
}

// ---------------------------------------------------------------------------
// Projection (unchanged from R1): dst[b,n,k] = x[n,b,:] . W[k,:] + bias
// ---------------------------------------------------------------------------
__global__ __launch_bounds__(256) void proj_kernel(
    const float* __restrict__ q, const float* __restrict__ k,
    const float* __restrict__ v,
    const float* __restrict__ Wq, const float* __restrict__ bq,
    const float* __restrict__ Wk, const float* __restrict__ bk,
    const float* __restrict__ Wv, const float* __restrict__ bv)
{
    __shared__ float sX[64][68];
    __shared__ float sW[64][68];
    __shared__ float sB[64];

    const float* x; const float* W; const float* bias; float* dst;
    if (blockIdx.y == 0)      { x = q; W = Wq; bias = bq; dst = g_qp; }
    else if (blockIdx.y == 1) { x = k; W = Wk; bias = bk; dst = g_kp; }
    else                      { x = v; W = Wv; bias = bv; dst = g_vp; }

    const int tid  = threadIdx.x;
    const int row0 = blockIdx.x * 64;

    #pragma unroll
    for (int it = 0; it < 4; it++) {
        int idx = tid + it * 256;
        int r = idx >> 4, c4 = idx & 15;
        float4 xv = reinterpret_cast<const float4*>(x + (size_t)(row0 + r) * HH)[c4];
        *reinterpret_cast<float4*>(&sX[r][c4 * 4]) = xv;
        float4 wv = reinterpret_cast<const float4*>(W + (size_t)r * HH)[c4];
        *reinterpret_cast<float4*>(&sW[r][c4 * 4]) = wv;
    }
    if (tid < 64) sB[tid] = bias[tid];
    __syncthreads();

    const int kk = tid & 15;
    const int rg = tid >> 4;

    float acc[4][4];
    #pragma unroll
    for (int j = 0; j < 4; j++)
        #pragma unroll
        for (int i = 0; i < 4; i++) acc[j][i] = 0.f;

    #pragma unroll
    for (int h = 0; h < HH; h += 4) {
        float4 xr[4], wr[4];
        #pragma unroll
        for (int j = 0; j < 4; j++)
            xr[j] = *reinterpret_cast<const float4*>(&sX[rg * 4 + j][h]);
        #pragma unroll
        for (int i = 0; i < 4; i++)
            wr[i] = *reinterpret_cast<const float4*>(&sW[kk + i * 16][h]);
        #pragma unroll
        for (int j = 0; j < 4; j++)
            #pragma unroll
            for (int i = 0; i < 4; i++)
                acc[j][i] += xr[j].x * wr[i].x + xr[j].y * wr[i].y
                           + xr[j].z * wr[i].z + xr[j].w * wr[i].w;
    }

    #pragma unroll
    for (int j = 0; j < 4; j++) {
        int grow = row0 + rg * 4 + j;
        int n = grow >> 7;
        int b = grow & 127;
        float* orow = dst + ((size_t)b * NN + n) * HH;
        #pragma unroll
        for (int i = 0; i < 4; i++) {
            int kcol = kk + i * 16;
            orow[kcol] = acc[j][i] + sB[kcol];
        }
    }
}

// ---------------------------------------------------------------------------
// Attention with tf32 mma.sync. CTA = 64 n-rows x one batch. 256 threads.
// ---------------------------------------------------------------------------
// smem float offsets
#define OQ 0                      // 64 x 68
#define OK_ 4352                  // 128 x 68
#define OV 13056                  // 128 x 72
#define OA 22272                  // 64 x 516
#define OS 55296                  // 2 x 64 partial row sums
#define OI 55424                  // 64 inverse sums
#define SMEM_FLOATS 55488

__global__ __launch_bounds__(256, 1) void attn_kernel(
    const float* __restrict__ mask,
    float* __restrict__ out,     // [N,B,H]
    float* __restrict__ Aout)    // [B,N,N]
{
    extern __shared__ float sm[];
    float*    sAf = sm + OA;
    uint32_t* sQu = reinterpret_cast<uint32_t*>(sm + OQ);
    uint32_t* sKu = reinterpret_cast<uint32_t*>(sm + OK_);
    uint32_t* sVu = reinterpret_cast<uint32_t*>(sm + OV);
    uint32_t* sAu = reinterpret_cast<uint32_t*>(sm + OA);

    const int tid  = threadIdx.x;
    const int w    = tid >> 5;
    const int lane = tid & 31;
    const int lx   = lane & 3;
    const int ly   = lane >> 2;
    const int stripe = w & 3;
    const int half   = w >> 2;
    const int row0 = stripe * 16;
    const int r0 = row0 + ly, r1 = r0 + 8;

    const int n0 = blockIdx.x * 64;
    const int b  = blockIdx.y;

    const float* qp = g_qp + (size_t)b * NN * HH;
    const float* kp = g_kp + (size_t)b * NN * HH;
    const float* vp = g_vp + (size_t)b * NN * HH;
    const float* mbase = mask + ((size_t)b * NN + n0) * NN;

    // Load Q tile (64 x 64) with tf32 rounding
    #pragma unroll
    for (int it = 0; it < 4; it++) {
        int idx = tid + it * 256;
        int r = idx >> 4, c4 = idx & 15;
        float4 t = *reinterpret_cast<const float4*>(qp + (size_t)(n0 + r) * HH + c4 * 4);
        uint4 u = { tf32r(t.x), tf32r(t.y), tf32r(t.z), tf32r(t.w) };
        *reinterpret_cast<uint4*>(&sQu[r * 68 + c4 * 4]) = u;
    }

    float oacc[4][4];
    #pragma unroll
    for (int t = 0; t < 4; t++)
        #pragma unroll
        for (int i = 0; i < 4; i++) oacc[t][i] = 0.f;

    float rsum0 = 0.f, rsum1 = 0.f;

    for (int c = 0; c < 4; c++) {
        const int mt = c * 128;
        __syncthreads();   // prev chunk's MMAs done with sK/sV (and Q visible on c=0)

        // Load K chunk (128x64, stride 68) and V chunk (128x64, stride 72)
        #pragma unroll
        for (int it = 0; it < 8; it++) {
            int idx = tid + it * 256;
            int r = idx >> 4, c4 = idx & 15;
            float4 t = *reinterpret_cast<const float4*>(kp + (size_t)(mt + r) * HH + c4 * 4);
            uint4 u = { tf32r(t.x), tf32r(t.y), tf32r(t.z), tf32r(t.w) };
            *reinterpret_cast<uint4*>(&sKu[r * 68 + c4 * 4]) = u;
            float4 s = *reinterpret_cast<const float4*>(vp + (size_t)(mt + r) * HH + c4 * 4);
            uint4 v = { tf32r(s.x), tf32r(s.y), tf32r(s.z), tf32r(s.w) };
            *reinterpret_cast<uint4*>(&sVu[r * 72 + c4 * 4]) = v;
        }
        __syncthreads();

        // ---- S = Q K^T for this warp's 16-row stripe, 64-col half ----
        float sacc[8][4];
        #pragma unroll
        for (int t = 0; t < 8; t++)
            #pragma unroll
            for (int i = 0; i < 4; i++) sacc[t][i] = 0.f;

        #pragma unroll
        for (int k0 = 0; k0 < 64; k0 += 8) {
            uint32_t a[4];
            a[0] = sQu[r0 * 68 + k0 + lx];
            a[1] = sQu[r1 * 68 + k0 + lx];
            a[2] = sQu[r0 * 68 + k0 + lx + 4];
            a[3] = sQu[r1 * 68 + k0 + lx + 4];
            #pragma unroll
            for (int t = 0; t < 8; t++) {
                int key = half * 64 + t * 8 + ly;
                uint32_t b0 = sKu[key * 68 + k0 + lx];
                uint32_t b1 = sKu[key * 68 + k0 + 4 + lx];
                mma_tf32(sacc[t], a, b0, b1);
            }
        }

        // ---- e = exp(S/8) * mask, in-register; accumulate rowsums; store sA ----
        #pragma unroll
        for (int t = 0; t < 8; t++) {
            int gc = mt + half * 64 + t * 8 + 2 * lx;
            float2 m0 = *reinterpret_cast<const float2*>(mbase + (size_t)r0 * NN + gc);
            float2 m1 = *reinterpret_cast<const float2*>(mbase + (size_t)r1 * NN + gc);
            float e00 = __expf(sacc[t][0] * SCALE) * m0.x;
            float e01 = __expf(sacc[t][1] * SCALE) * m0.y;
            float e10 = __expf(sacc[t][2] * SCALE) * m1.x;
            float e11 = __expf(sacc[t][3] * SCALE) * m1.y;
            e00 = __uint_as_float(tf32r(e00));
            e01 = __uint_as_float(tf32r(e01));
            e10 = __uint_as_float(tf32r(e10));
            e11 = __uint_as_float(tf32r(e11));
            rsum0 += e00 + e01;
            rsum1 += e10 + e11;
            *reinterpret_cast<float2*>(&sAf[r0 * 516 + gc]) = make_float2(e00, e01);
            *reinterpret_cast<float2*>(&sAf[r1 * 516 + gc]) = make_float2(e10, e11);
        }
        __syncthreads();   // e visible to all warps

        // ---- AV accumulate: oacc += e_chunk @ V_chunk ----
        #pragma unroll
        for (int k0 = 0; k0 < 128; k0 += 8) {
            uint32_t a[4];
            int gc = mt + k0;
            a[0] = sAu[r0 * 516 + gc + lx];
            a[1] = sAu[r1 * 516 + gc + lx];
            a[2] = sAu[r0 * 516 + gc + lx + 4];
            a[3] = sAu[r1 * 516 + gc + lx + 4];
            #pragma unroll
            for (int t = 0; t < 4; t++) {
                int h = half * 32 + t * 8 + ly;
                uint32_t b0 = sVu[(k0 + lx) * 72 + h];
                uint32_t b1 = sVu[(k0 + 4 + lx) * 72 + h];
                mma_tf32(oacc[t], a, b0, b1);
            }
        }
    }

    // ---- row sums -> inverse ----
    rsum0 += __shfl_xor_sync(0xffffffff, rsum0, 1);
    rsum0 += __shfl_xor_sync(0xffffffff, rsum0, 2);
    rsum1 += __shfl_xor_sync(0xffffffff, rsum1, 1);
    rsum1 += __shfl_xor_sync(0xffffffff, rsum1, 2);
    if (lx == 0) {
        sm[OS + half * 64 + r0] = rsum0;
        sm[OS + half * 64 + r1] = rsum1;
    }
    __syncthreads();
    if (tid < 64) {
        float s = sm[OS + tid] + sm[OS + 64 + tid];
        sm[OI + tid] = (s == 0.f) ? 1.f : (1.f / s);
    }
    __syncthreads();

    // ---- write normalized A (coalesced float4) ----
    {
        int row = tid >> 2, s4 = tid & 3;
        float inv = sm[OI + row];
        float4* grow = reinterpret_cast<float4*>(Aout + ((size_t)b * NN + n0 + row) * NN);
        #pragma unroll
        for (int i = 0; i < 32; i++) {
            int c4 = s4 + 4 * i;
            float4 t = *reinterpret_cast<const float4*>(&sAf[row * 516 + 4 * c4]);
            t.x *= inv; t.y *= inv; t.z *= inv; t.w *= inv;
            grow[c4] = t;
        }
    }

    // ---- stage out through smem (reuse sK region), then coalesced write ----
    {
        float* sO = sm + OK_;   // 64 x 68
        float i0 = sm[OI + r0], i1 = sm[OI + r1];
        #pragma unroll
        for (int t = 0; t < 4; t++) {
            int h = half * 32 + t * 8 + 2 * lx;
            *reinterpret_cast<float2*>(&sO[r0 * 68 + h]) =
                make_float2(oacc[t][0] * i0, oacc[t][1] * i0);
            *reinterpret_cast<float2*>(&sO[r1 * 68 + h]) =
                make_float2(oacc[t][2] * i1, oacc[t][3] * i1);
        }
        __syncthreads();
        #pragma unroll
        for (int it = 0; it < 4; it++) {
            int idx = tid + it * 256;
            int row = idx >> 4, c4 = idx & 15;
            float4 t = *reinterpret_cast<const float4*>(&sO[row * 68 + 4 * c4]);
            *reinterpret_cast<float4*>(out + ((size_t)(n0 + row) * BB + b) * HH + 4 * c4) = t;
        }
    }
}

// ---------------------------------------------------------------------------
extern "C" void kernel_launch(void* const* d_in, const int* in_sizes, int n_in,
                              void* d_out, int out_size)
{
    const float* q    = (const float*)d_in[0];
    const float* k    = (const float*)d_in[1];
    const float* v    = (const float*)d_in[2];
    const float* mask = (const float*)d_in[3];
    const float* Wq   = (const float*)d_in[4];
    const float* bq   = (const float*)d_in[5];
    const float* Wk   = (const float*)d_in[6];
    const float* bk   = (const float*)d_in[7];
    const float* Wv   = (const float*)d_in[8];
    const float* bv   = (const float*)d_in[9];

    float* out  = (float*)d_out;                         // [N,B,H] first
    float* Aout = (float*)d_out + (size_t)NN * BB * HH;  // then [B,N,N]

    const int smem_bytes = SMEM_FLOATS * 4;
    cudaFuncSetAttribute(attn_kernel, cudaFuncAttributeMaxDynamicSharedMemorySize,
                         smem_bytes);

    proj_kernel<<<dim3((NN * BB) / 64, 3), 256>>>(q, k, v, Wq, bq, Wk, bk, Wv, bv);
    attn_kernel<<<dim3(NN / 64, BB), 256, smem_bytes>>>(mask, out, Aout);
}

// round 4
// speedup vs baseline: 1.7929x; 1.0768x over previous
#include <cuda_runtime.h>
#include <cstdint>

#define HH 64
#define NN 512
#define BB 128
#define SCALE 0.125f

__device__ float g_qp[BB * NN * HH];
__device__ float g_kp[BB * NN * HH];
__device__ float g_vp[BB * NN * HH];

// ---------------- helpers ----------------
__device__ __forceinline__ uint32_t tf32r(float f) {
    uint32_t u;
    asm("cvt.rna.tf32.f32 %0, %1;" : "=r"(u) : "f"(f));
    return u;
}
__device__ __forceinline__ void mma_tf32(float* d, const uint32_t* a,
                                         uint32_t b0, uint32_t b1) {
    asm volatile(
        "mma.sync.aligned.m16n8k8.row.col.f32.tf32.tf32.f32 "
        "{%0,%1,%2,%3}, {%4,%5,%6,%7}, {%8,%9}, {%0,%1,%2,%3};"
        : "+f"(d[0]), "+f"(d[1]), "+f"(d[2]), "+f"(d[3])
        : "r"(a[0]), "r"(a[1]), "r"(a[2]), "r"(a[3]), "r"(b0), "r"(b1));
}

// ---------------------------------------------------------------------------
// Projection with tf32 mma: dst[b,n,k] = x[n,b,:] . W[k,:] + bias
// CTA: 128 flat rows x 64 cols. 256 threads, 8 warps (16 rows each).
// ---------------------------------------------------------------------------
__global__ __launch_bounds__(256, 2) void proj_kernel(
    const float* __restrict__ q, const float* __restrict__ k,
    const float* __restrict__ v,
    const float* __restrict__ Wq, const float* __restrict__ bq,
    const float* __restrict__ Wk, const float* __restrict__ bk,
    const float* __restrict__ Wv, const float* __restrict__ bv)
{
    __shared__ uint32_t sX[128 * 68];
    __shared__ uint32_t sW[64 * 68];
    __shared__ float    sB[64];

    const float* x; const float* W; const float* bias; float* dst;
    if (blockIdx.y == 0)      { x = q; W = Wq; bias = bq; dst = g_qp; }
    else if (blockIdx.y == 1) { x = k; W = Wk; bias = bk; dst = g_kp; }
    else                      { x = v; W = Wv; bias = bv; dst = g_vp; }

    const int tid  = threadIdx.x;
    const int row0 = blockIdx.x * 128;

    // Load 128x64 X tile (tf32-rounded)
    #pragma unroll
    for (int it = 0; it < 8; it++) {
        int idx = tid + it * 256;
        int r = idx >> 4, c4 = idx & 15;
        float4 t = *reinterpret_cast<const float4*>(x + (size_t)(row0 + r) * HH + c4 * 4);
        uint4 u = { tf32r(t.x), tf32r(t.y), tf32r(t.z), tf32r(t.w) };
        *reinterpret_cast<uint4*>(&sX[r * 68 + c4 * 4]) = u;
    }
    // Load 64x64 W (tf32-rounded)
    #pragma unroll
    for (int it = 0; it < 4; it++) {
        int idx = tid + it * 256;
        int r = idx >> 4, c4 = idx & 15;
        float4 t = *reinterpret_cast<const float4*>(W + (size_t)r * HH + c4 * 4);
        uint4 u = { tf32r(t.x), tf32r(t.y), tf32r(t.z), tf32r(t.w) };
        *reinterpret_cast<uint4*>(&sW[r * 68 + c4 * 4]) = u;
    }
    if (tid < 64) sB[tid] = bias[tid];
    __syncthreads();

    const int w    = tid >> 5;
    const int lane = tid & 31;
    const int lx   = lane & 3;
    const int ly   = lane >> 2;
    const int r0   = w * 16 + ly;
    const int r1   = r0 + 8;

    float acc[8][4];
    #pragma unroll
    for (int t = 0; t < 8; t++)
        #pragma unroll
        for (int i = 0; i < 4; i++) acc[t][i] = 0.f;

    #pragma unroll
    for (int k0 = 0; k0 < 64; k0 += 8) {
        uint32_t a[4];
        a[0] = sX[r0 * 68 + k0 + lx];
        a[1] = sX[r1 * 68 + k0 + lx];
        a[2] = sX[r0 * 68 + k0 + lx + 4];
        a[3] = sX[r1 * 68 + k0 + lx + 4];
        #pragma unroll
        for (int t = 0; t < 8; t++) {
            uint32_t b0 = sW[(t * 8 + ly) * 68 + k0 + lx];
            uint32_t b1 = sW[(t * 8 + ly) * 68 + k0 + 4 + lx];
            mma_tf32(acc[t], a, b0, b1);
        }
    }

    // Epilogue: bias add + scattered float2 stores into [B,N,H]
    int g0 = row0 + r0, g1 = row0 + r1;
    float* orow0 = dst + ((size_t)(g0 & 127) * NN + (g0 >> 7)) * HH;
    float* orow1 = dst + ((size_t)(g1 & 127) * NN + (g1 >> 7)) * HH;
    #pragma unroll
    for (int t = 0; t < 8; t++) {
        int c0 = t * 8 + 2 * lx;
        float b0 = sB[c0], b1 = sB[c0 + 1];
        *reinterpret_cast<float2*>(orow0 + c0) = make_float2(acc[t][0] + b0, acc[t][1] + b1);
        *reinterpret_cast<float2*>(orow1 + c0) = make_float2(acc[t][2] + b0, acc[t][3] + b1);
    }
}

// ---------------------------------------------------------------------------
// Attention: CTA = 32 n-rows x one batch, 8 chunks of 64 keys, single pass.
// 8 warps = 2 row-stripes x 4 col-quads. 2 CTAs/SM.
// ---------------------------------------------------------------------------
// smem float offsets
#define OQ 0                        // 32 x 68
#define OK_ 2176                    // 64 x 68
#define OV 6528                     // 64 x 68
#define OA 10880                    // 32 x 516
#define OS 27392                    // 128 partial row sums (4 quads x 32 rows)
#define OI 27520                    // 32 inverse sums
#define SMEM_FLOATS 27552

__global__ __launch_bounds__(256, 2) void attn_kernel(
    const float* __restrict__ mask,
    float* __restrict__ out,     // [N,B,H]
    float* __restrict__ Aout)    // [B,N,N]
{
    extern __shared__ float sm[];
    float*    sAf = sm + OA;
    uint32_t* sQu = reinterpret_cast<uint32_t*>(sm + OQ);
    uint32_t* sKu = reinterpret_cast<uint32_t*>(sm + OK_);
    uint32_t* sVu = reinterpret_cast<uint32_t*>(sm + OV);
    uint32_t* sAu = reinterpret_cast<uint32_t*>(sm + OA);

    const int tid  = threadIdx.x;
    const int w    = tid >> 5;
    const int lane = tid & 31;
    const int lx   = lane & 3;
    const int ly   = lane >> 2;
    const int stripe = w & 1;        // 16-row stripe
    const int quad   = w >> 1;       // 16-col group
    const int r0 = stripe * 16 + ly, r1 = r0 + 8;

    const int n0 = blockIdx.x * 32;
    const int b  = blockIdx.y;

    const float* qp = g_qp + (size_t)b * NN * HH;
    const float* kp = g_kp + (size_t)b * NN * HH;
    const float* vp = g_vp + (size_t)b * NN * HH;
    const float* mbase = mask + ((size_t)b * NN + n0) * NN;

    // Load Q tile (32 x 64), tf32-rounded
    #pragma unroll
    for (int it = 0; it < 2; it++) {
        int idx = tid + it * 256;
        int r = idx >> 4, c4 = idx & 15;
        float4 t = *reinterpret_cast<const float4*>(qp + (size_t)(n0 + r) * HH + c4 * 4);
        uint4 u = { tf32r(t.x), tf32r(t.y), tf32r(t.z), tf32r(t.w) };
        *reinterpret_cast<uint4*>(&sQu[r * 68 + c4 * 4]) = u;
    }

    float oacc[2][4];
    #pragma unroll
    for (int t = 0; t < 2; t++)
        #pragma unroll
        for (int i = 0; i < 4; i++) oacc[t][i] = 0.f;

    float rsum0 = 0.f, rsum1 = 0.f;

    for (int c = 0; c < 8; c++) {
        const int mt = c * 64;
        __syncthreads();   // prev AV done with sK/sV (and Q visible on c=0)

        // Load K,V chunks (64 x 64 each), tf32-rounded
        #pragma unroll
        for (int it = 0; it < 4; it++) {
            int idx = tid + it * 256;
            int r = idx >> 4, c4 = idx & 15;
            float4 t = *reinterpret_cast<const float4*>(kp + (size_t)(mt + r) * HH + c4 * 4);
            uint4 uk = { tf32r(t.x), tf32r(t.y), tf32r(t.z), tf32r(t.w) };
            *reinterpret_cast<uint4*>(&sKu[r * 68 + c4 * 4]) = uk;
            float4 s = *reinterpret_cast<const float4*>(vp + (size_t)(mt + r) * HH + c4 * 4);
            uint4 uv = { tf32r(s.x), tf32r(s.y), tf32r(s.z), tf32r(s.w) };
            *reinterpret_cast<uint4*>(&sVu[r * 68 + c4 * 4]) = uv;
        }
        __syncthreads();

        // ---- S = Q K^T : 16 rows x 16 keys per warp ----
        float sacc[2][4];
        #pragma unroll
        for (int t = 0; t < 2; t++)
            #pragma unroll
            for (int i = 0; i < 4; i++) sacc[t][i] = 0.f;

        #pragma unroll
        for (int k0 = 0; k0 < 64; k0 += 8) {
            uint32_t a[4];
            a[0] = sQu[r0 * 68 + k0 + lx];
            a[1] = sQu[r1 * 68 + k0 + lx];
            a[2] = sQu[r0 * 68 + k0 + lx + 4];
            a[3] = sQu[r1 * 68 + k0 + lx + 4];
            #pragma unroll
            for (int t = 0; t < 2; t++) {
                int key = quad * 16 + t * 8 + ly;
                uint32_t b0 = sKu[key * 68 + k0 + lx];
                uint32_t b1 = sKu[key * 68 + k0 + 4 + lx];
                mma_tf32(sacc[t], a, b0, b1);
            }
        }

        // ---- e = exp(S/8)*mask ; rowsums ; stage into sA ----
        #pragma unroll
        for (int t = 0; t < 2; t++) {
            int gc = mt + quad * 16 + t * 8 + 2 * lx;
            float2 m0 = *reinterpret_cast<const float2*>(mbase + (size_t)r0 * NN + gc);
            float2 m1 = *reinterpret_cast<const float2*>(mbase + (size_t)r1 * NN + gc);
            float e00 = __uint_as_float(tf32r(__expf(sacc[t][0] * SCALE) * m0.x));
            float e01 = __uint_as_float(tf32r(__expf(sacc[t][1] * SCALE) * m0.y));
            float e10 = __uint_as_float(tf32r(__expf(sacc[t][2] * SCALE) * m1.x));
            float e11 = __uint_as_float(tf32r(__expf(sacc[t][3] * SCALE) * m1.y));
            rsum0 += e00 + e01;
            rsum1 += e10 + e11;
            *reinterpret_cast<float2*>(&sAf[r0 * 516 + gc]) = make_float2(e00, e01);
            *reinterpret_cast<float2*>(&sAf[r1 * 516 + gc]) = make_float2(e10, e11);
        }
        __syncthreads();

        // ---- AV accumulate: 16 rows x 16 h-cols per warp, k over 64 ----
        #pragma unroll
        for (int k0 = 0; k0 < 64; k0 += 8) {
            uint32_t a[4];
            a[0] = sAu[r0 * 516 + mt + k0 + lx];
            a[1] = sAu[r1 * 516 + mt + k0 + lx];
            a[2] = sAu[r0 * 516 + mt + k0 + lx + 4];
            a[3] = sAu[r1 * 516 + mt + k0 + lx + 4];
            #pragma unroll
            for (int t = 0; t < 2; t++) {
                int h = quad * 16 + t * 8 + ly;
                uint32_t b0 = sVu[(k0 + lx) * 68 + h];
                uint32_t b1 = sVu[(k0 + 4 + lx) * 68 + h];
                mma_tf32(oacc[t], a, b0, b1);
            }
        }
    }

    // ---- row sums -> inverse ----
    rsum0 += __shfl_xor_sync(0xffffffff, rsum0, 1);
    rsum0 += __shfl_xor_sync(0xffffffff, rsum0, 2);
    rsum1 += __shfl_xor_sync(0xffffffff, rsum1, 1);
    rsum1 += __shfl_xor_sync(0xffffffff, rsum1, 2);
    if (lx == 0) {
        sm[OS + quad * 32 + r0] = rsum0;
        sm[OS + quad * 32 + r1] = rsum1;
    }
    __syncthreads();
    if (tid < 32) {
        float s = sm[OS + tid] + sm[OS + 32 + tid] + sm[OS + 64 + tid] + sm[OS + 96 + tid];
        sm[OI + tid] = (s == 0.f) ? 1.f : (1.f / s);
    }
    __syncthreads();

    // ---- write normalized A (coalesced float4) ----
    {
        int row = tid >> 3, s8 = tid & 7;
        float inv = sm[OI + row];
        float4* grow = reinterpret_cast<float4*>(Aout + ((size_t)b * NN + n0 + row) * NN);
        #pragma unroll
        for (int i = 0; i < 16; i++) {
            int c4 = s8 + 8 * i;
            float4 t = *reinterpret_cast<const float4*>(&sAf[row * 516 + 4 * c4]);
            t.x *= inv; t.y *= inv; t.z *= inv; t.w *= inv;
            grow[c4] = t;
        }
    }

    // ---- stage out through smem (reuse sK region), coalesced write ----
    {
        float* sO = sm + OK_;   // 32 x 68 fits in sK region
        float i0 = sm[OI + r0], i1 = sm[OI + r1];
        #pragma unroll
        for (int t = 0; t < 2; t++) {
            int h = quad * 16 + t * 8 + 2 * lx;
            *reinterpret_cast<float2*>(&sO[r0 * 68 + h]) =
                make_float2(oacc[t][0] * i0, oacc[t][1] * i0);
            *reinterpret_cast<float2*>(&sO[r1 * 68 + h]) =
                make_float2(oacc[t][2] * i1, oacc[t][3] * i1);
        }
        __syncthreads();
        #pragma unroll
        for (int it = 0; it < 2; it++) {
            int idx = tid + it * 256;
            int row = idx >> 4, c4 = idx & 15;
            float4 t = *reinterpret_cast<const float4*>(&sO[row * 68 + 4 * c4]);
            *reinterpret_cast<float4*>(out + ((size_t)(n0 + row) * BB + b) * HH + 4 * c4) = t;
        }
    }
}

// ---------------------------------------------------------------------------
extern "C" void kernel_launch(void* const* d_in, const int* in_sizes, int n_in,
                              void* d_out, int out_size)
{
    const float* q    = (const float*)d_in[0];
    const float* k    = (const float*)d_in[1];
    const float* v    = (const float*)d_in[2];
    const float* mask = (const float*)d_in[3];
    const float* Wq   = (const float*)d_in[4];
    const float* bq   = (const float*)d_in[5];
    const float* Wk   = (const float*)d_in[6];
    const float* bk   = (const float*)d_in[7];
    const float* Wv   = (const float*)d_in[8];
    const float* bv   = (const float*)d_in[9];

    float* out  = (float*)d_out;                         // [N,B,H] first
    float* Aout = (float*)d_out + (size_t)NN * BB * HH;  // then [B,N,N]

    const int smem_bytes = SMEM_FLOATS * 4;
    cudaFuncSetAttribute(attn_kernel, cudaFuncAttributeMaxDynamicSharedMemorySize,
                         smem_bytes);

    proj_kernel<<<dim3((NN * BB) / 128, 3), 256>>>(q, k, v, Wq, bq, Wk, bk, Wv, bv);
    attn_kernel<<<dim3(NN / 32, BB), 256, smem_bytes>>>(mask, out, Aout);
}

// round 5
// speedup vs baseline: 1.8027x; 1.0054x over previous
#include <cuda_runtime.h>
#include <cstdint>

#define HH 64
#define NN 512
#define BB 128
#define SCALE 0.125f

__device__ float g_qp[BB * NN * HH];
__device__ float g_kp[BB * NN * HH];
__device__ float g_vp[BB * NN * HH];

// ---------------- helpers ----------------
__device__ __forceinline__ uint32_t tf32r(float f) {
    uint32_t u;
    asm("cvt.rna.tf32.f32 %0, %1;" : "=r"(u) : "f"(f));
    return u;
}
__device__ __forceinline__ void mma_tf32(float* d, const uint32_t* a,
                                         uint32_t b0, uint32_t b1) {
    asm volatile(
        "mma.sync.aligned.m16n8k8.row.col.f32.tf32.tf32.f32 "
        "{%0,%1,%2,%3}, {%4,%5,%6,%7}, {%8,%9}, {%0,%1,%2,%3};"
        : "+f"(d[0]), "+f"(d[1]), "+f"(d[2]), "+f"(d[3])
        : "r"(a[0]), "r"(a[1]), "r"(a[2]), "r"(a[3]), "r"(b0), "r"(b1));
}
__device__ __forceinline__ void cpa16(uint32_t saddr, const void* gptr) {
    asm volatile("cp.async.cg.shared.global [%0], [%1], 16;" :: "r"(saddr), "l"(gptr));
}
__device__ __forceinline__ void cpa_commit() {
    asm volatile("cp.async.commit_group;" ::: "memory");
}
__device__ __forceinline__ void cpa_wait1() {
    asm volatile("cp.async.wait_group 1;" ::: "memory");
}

// ---------------------------------------------------------------------------
// Projection with tf32 mma: dst[b,n,k] = x[n,b,:] . W[k,:] + bias
// ---------------------------------------------------------------------------
__global__ __launch_bounds__(256, 2) void proj_kernel(
    const float* __restrict__ q, const float* __restrict__ k,
    const float* __restrict__ v,
    const float* __restrict__ Wq, const float* __restrict__ bq,
    const float* __restrict__ Wk, const float* __restrict__ bk,
    const float* __restrict__ Wv, const float* __restrict__ bv)
{
    __shared__ uint32_t sX[128 * 68];
    __shared__ uint32_t sW[64 * 68];
    __shared__ float    sB[64];

    const float* x; const float* W; const float* bias; float* dst;
    if (blockIdx.y == 0)      { x = q; W = Wq; bias = bq; dst = g_qp; }
    else if (blockIdx.y == 1) { x = k; W = Wk; bias = bk; dst = g_kp; }
    else                      { x = v; W = Wv; bias = bv; dst = g_vp; }

    const int tid  = threadIdx.x;
    const int row0 = blockIdx.x * 128;

    #pragma unroll
    for (int it = 0; it < 8; it++) {
        int idx = tid + it * 256;
        int r = idx >> 4, c4 = idx & 15;
        float4 t = *reinterpret_cast<const float4*>(x + (size_t)(row0 + r) * HH + c4 * 4);
        uint4 u = { tf32r(t.x), tf32r(t.y), tf32r(t.z), tf32r(t.w) };
        *reinterpret_cast<uint4*>(&sX[r * 68 + c4 * 4]) = u;
    }
    #pragma unroll
    for (int it = 0; it < 4; it++) {
        int idx = tid + it * 256;
        int r = idx >> 4, c4 = idx & 15;
        float4 t = *reinterpret_cast<const float4*>(W + (size_t)r * HH + c4 * 4);
        uint4 u = { tf32r(t.x), tf32r(t.y), tf32r(t.z), tf32r(t.w) };
        *reinterpret_cast<uint4*>(&sW[r * 68 + c4 * 4]) = u;
    }
    if (tid < 64) sB[tid] = bias[tid];
    __syncthreads();

    const int w    = tid >> 5;
    const int lane = tid & 31;
    const int lx   = lane & 3;
    const int ly   = lane >> 2;
    const int r0   = w * 16 + ly;
    const int r1   = r0 + 8;

    float acc[8][4];
    #pragma unroll
    for (int t = 0; t < 8; t++)
        #pragma unroll
        for (int i = 0; i < 4; i++) acc[t][i] = 0.f;

    #pragma unroll
    for (int k0 = 0; k0 < 64; k0 += 8) {
        uint32_t a[4];
        a[0] = sX[r0 * 68 + k0 + lx];
        a[1] = sX[r1 * 68 + k0 + lx];
        a[2] = sX[r0 * 68 + k0 + lx + 4];
        a[3] = sX[r1 * 68 + k0 + lx + 4];
        #pragma unroll
        for (int t = 0; t < 8; t++) {
            uint32_t b0 = sW[(t * 8 + ly) * 68 + k0 + lx];
            uint32_t b1 = sW[(t * 8 + ly) * 68 + k0 + 4 + lx];
            mma_tf32(acc[t], a, b0, b1);
        }
    }

    int g0 = row0 + r0, g1 = row0 + r1;
    float* orow0 = dst + ((size_t)(g0 & 127) * NN + (g0 >> 7)) * HH;
    float* orow1 = dst + ((size_t)(g1 & 127) * NN + (g1 >> 7)) * HH;
    #pragma unroll
    for (int t = 0; t < 8; t++) {
        int c0 = t * 8 + 2 * lx;
        float b0 = sB[c0], b1 = sB[c0 + 1];
        *reinterpret_cast<float2*>(orow0 + c0) = make_float2(acc[t][0] + b0, acc[t][1] + b1);
        *reinterpret_cast<float2*>(orow1 + c0) = make_float2(acc[t][2] + b0, acc[t][3] + b1);
    }
}

// ---------------------------------------------------------------------------
// Attention: CTA = 32 n-rows x one batch. 16 chunks of 32 keys.
// cp.async double-buffered K/V, mask prefetched one chunk ahead.
// 8 warps = 2 row-stripes x 4 col-quads (8 keys / 16 h-cols per quad).
// ---------------------------------------------------------------------------
// smem float offsets
#define OQ   0                      // 32 x 68
#define OK0  2176                   // 32 x 68
#define OK1  4352                   // 32 x 68
#define OV0  6528                   // 32 x 72
#define OV1  8832                   // 32 x 72
#define OA   11136                  // 32 x 516
#define OS   27648                  // 128 partial row sums
#define OI   27776                  // 32 inverse sums
#define SMEM_FLOATS 27808

__global__ __launch_bounds__(256, 2) void attn_kernel(
    const float* __restrict__ mask,
    float* __restrict__ out,     // [N,B,H]
    float* __restrict__ Aout)    // [B,N,N]
{
    extern __shared__ float sm[];
    float*    sAf = sm + OA;
    uint32_t* sQu = reinterpret_cast<uint32_t*>(sm + OQ);
    uint32_t* sAu = reinterpret_cast<uint32_t*>(sm + OA);
    const uint32_t sbase = (uint32_t)__cvta_generic_to_shared(sm);

    const int tid  = threadIdx.x;
    const int w    = tid >> 5;
    const int lane = tid & 31;
    const int lx   = lane & 3;
    const int ly   = lane >> 2;
    const int stripe = w & 1;
    const int quad   = w >> 1;
    const int r0 = stripe * 16 + ly, r1 = r0 + 8;

    const int n0 = blockIdx.x * 32;
    const int b  = blockIdx.y;

    const float* qp = g_qp + (size_t)b * NN * HH;
    const float* kp = g_kp + (size_t)b * NN * HH;
    const float* vp = g_vp + (size_t)b * NN * HH;
    const float* mbase = mask + ((size_t)b * NN + n0) * NN;

    // ---- prologue: Q tile to smem (tf32-rounded), K/V chunks 0,1 via cp.async
    #pragma unroll
    for (int it = 0; it < 2; it++) {
        int idx = tid + it * 256;
        int r = idx >> 4, c4 = idx & 15;
        float4 t = *reinterpret_cast<const float4*>(qp + (size_t)(n0 + r) * HH + c4 * 4);
        uint4 u = { tf32r(t.x), tf32r(t.y), tf32r(t.z), tf32r(t.w) };
        *reinterpret_cast<uint4*>(&sQu[r * 68 + c4 * 4]) = u;
    }
    {
        int idx = tid;                 // 32x64 floats = 512 float4; 2 per thread
        #pragma unroll
        for (int it = 0; it < 2; it++) {
            int id = idx + it * 256;
            int r = id >> 4, c4 = id & 15;
            cpa16(sbase + (OK0 + r * 68 + c4 * 4) * 4, kp + (size_t)r * HH + c4 * 4);
            cpa16(sbase + (OV0 + r * 72 + c4 * 4) * 4, vp + (size_t)r * HH + c4 * 4);
        }
        cpa_commit();
        #pragma unroll
        for (int it = 0; it < 2; it++) {
            int id = idx + it * 256;
            int r = id >> 4, c4 = id & 15;
            cpa16(sbase + (OK1 + r * 68 + c4 * 4) * 4, kp + (size_t)(32 + r) * HH + c4 * 4);
            cpa16(sbase + (OV1 + r * 72 + c4 * 4) * 4, vp + (size_t)(32 + r) * HH + c4 * 4);
        }
        cpa_commit();
    }
    __syncthreads();   // sQ ready

    // ---- Q fragments to registers (held for entire kernel)
    uint32_t qf[8][4];
    #pragma unroll
    for (int kk = 0; kk < 8; kk++) {
        int k0 = kk * 8;
        qf[kk][0] = sQu[r0 * 68 + k0 + lx];
        qf[kk][1] = sQu[r1 * 68 + k0 + lx];
        qf[kk][2] = sQu[r0 * 68 + k0 + lx + 4];
        qf[kk][3] = sQu[r1 * 68 + k0 + lx + 4];
    }

    // mask prefetch for chunk 0
    float2 mbuf[2][2];
    {
        int gc = quad * 8 + 2 * lx;
        mbuf[0][0] = *reinterpret_cast<const float2*>(mbase + (size_t)r0 * NN + gc);
        mbuf[0][1] = *reinterpret_cast<const float2*>(mbase + (size_t)r1 * NN + gc);
    }

    float oacc[2][4];
    #pragma unroll
    for (int t = 0; t < 2; t++)
        #pragma unroll
        for (int i = 0; i < 4; i++) oacc[t][i] = 0.f;
    float rsum0 = 0.f, rsum1 = 0.f;

    const int colq = quad * 8 + 2 * lx;   // this thread's S-output column pair

    for (int c = 0; c < 16; c++) {
        const int p  = c & 1;
        const int mt = c * 32;
        const int OKp = p ? OK1 : OK0;
        const int OVp = p ? OV1 : OV0;
        uint32_t* sKu = reinterpret_cast<uint32_t*>(sm + OKp);
        uint32_t* sVu = reinterpret_cast<uint32_t*>(sm + OVp);

        cpa_wait1();
        __syncthreads();                  // chunk c data visible CTA-wide

        // prefetch mask for chunk c+1
        if (c + 1 < 16) {
            int gc = (c + 1) * 32 + colq;
            mbuf[(c + 1) & 1][0] = *reinterpret_cast<const float2*>(mbase + (size_t)r0 * NN + gc);
            mbuf[(c + 1) & 1][1] = *reinterpret_cast<const float2*>(mbase + (size_t)r1 * NN + gc);
        }

        // ---- S = Q K^T : 16 rows x 8 keys per warp (keys quad*8..+8)
        float sacc[4] = {0.f, 0.f, 0.f, 0.f};
        #pragma unroll
        for (int kk = 0; kk < 8; kk++) {
            int k0 = kk * 8;
            uint32_t b0 = tf32r(__uint_as_float(sKu[(quad * 8 + ly) * 68 + k0 + lx]));
            uint32_t b1 = tf32r(__uint_as_float(sKu[(quad * 8 + ly) * 68 + k0 + 4 + lx]));
            mma_tf32(sacc, qf[kk], b0, b1);
        }

        // ---- e = exp(S/8)*mask ; rowsums ; stage into sA
        {
            float2 m0 = mbuf[c & 1][0];
            float2 m1 = mbuf[c & 1][1];
            float e00 = __expf(sacc[0] * SCALE) * m0.x;
            float e01 = __expf(sacc[1] * SCALE) * m0.y;
            float e10 = __expf(sacc[2] * SCALE) * m1.x;
            float e11 = __expf(sacc[3] * SCALE) * m1.y;
            rsum0 += e00 + e01;
            rsum1 += e10 + e11;
            *reinterpret_cast<float2*>(&sAf[r0 * 516 + mt + colq]) = make_float2(e00, e01);
            *reinterpret_cast<float2*>(&sAf[r1 * 516 + mt + colq]) = make_float2(e10, e11);
        }
        __syncthreads();                  // e visible

        // ---- AV accumulate: 16 rows x 16 h-cols per warp, k over 32 keys
        #pragma unroll
        for (int k0 = 0; k0 < 32; k0 += 8) {
            uint32_t a[4];
            a[0] = sAu[r0 * 516 + mt + k0 + lx];
            a[1] = sAu[r1 * 516 + mt + k0 + lx];
            a[2] = sAu[r0 * 516 + mt + k0 + lx + 4];
            a[3] = sAu[r1 * 516 + mt + k0 + lx + 4];
            #pragma unroll
            for (int t = 0; t < 2; t++) {
                int h = quad * 16 + t * 8 + ly;
                uint32_t b0 = sVu[(k0 + lx) * 72 + h];
                uint32_t b1 = sVu[(k0 + 4 + lx) * 72 + h];
                mma_tf32(oacc[t], a, b0, b1);
            }
        }
        __syncthreads();                  // AV done: buffer p reusable

        // ---- issue cp.async for chunk c+2 into buffer p
        if (c + 2 < 16) {
            const int mt2 = (c + 2) * 32;
            #pragma unroll
            for (int it = 0; it < 2; it++) {
                int id = tid + it * 256;
                int r = id >> 4, c4 = id & 15;
                cpa16(sbase + (OKp + r * 68 + c4 * 4) * 4, kp + (size_t)(mt2 + r) * HH + c4 * 4);
                cpa16(sbase + (OVp + r * 72 + c4 * 4) * 4, vp + (size_t)(mt2 + r) * HH + c4 * 4);
            }
        }
        cpa_commit();
    }

    // ---- row sums -> inverse
    rsum0 += __shfl_xor_sync(0xffffffff, rsum0, 1);
    rsum0 += __shfl_xor_sync(0xffffffff, rsum0, 2);
    rsum1 += __shfl_xor_sync(0xffffffff, rsum1, 1);
    rsum1 += __shfl_xor_sync(0xffffffff, rsum1, 2);
    if (lx == 0) {
        sm[OS + quad * 32 + r0] = rsum0;
        sm[OS + quad * 32 + r1] = rsum1;
    }
    __syncthreads();
    if (tid < 32) {
        float s = sm[OS + tid] + sm[OS + 32 + tid] + sm[OS + 64 + tid] + sm[OS + 96 + tid];
        sm[OI + tid] = (s == 0.f) ? 1.f : (1.f / s);
    }
    __syncthreads();

    // ---- write normalized A (coalesced float4)
    {
        int row = tid >> 3, s8 = tid & 7;
        float inv = sm[OI + row];
        float4* grow = reinterpret_cast<float4*>(Aout + ((size_t)b * NN + n0 + row) * NN);
        #pragma unroll
        for (int i = 0; i < 16; i++) {
            int c4 = s8 + 8 * i;
            float4 t = *reinterpret_cast<const float4*>(&sAf[row * 516 + 4 * c4]);
            t.x *= inv; t.y *= inv; t.z *= inv; t.w *= inv;
            grow[c4] = t;
        }
    }

    // ---- stage out through smem (reuse K0 region), coalesced write
    {
        float* sO = sm + OK0;   // 32 x 68 fits
        float i0 = sm[OI + r0], i1 = sm[OI + r1];
        #pragma unroll
        for (int t = 0; t < 2; t++) {
            int h = quad * 16 + t * 8 + 2 * lx;
            *reinterpret_cast<float2*>(&sO[r0 * 68 + h]) =
                make_float2(oacc[t][0] * i0, oacc[t][1] * i0);
            *reinterpret_cast<float2*>(&sO[r1 * 68 + h]) =
                make_float2(oacc[t][2] * i1, oacc[t][3] * i1);
        }
        __syncthreads();
        #pragma unroll
        for (int it = 0; it < 2; it++) {
            int idx = tid + it * 256;
            int row = idx >> 4, c4 = idx & 15;
            float4 t = *reinterpret_cast<const float4*>(&sO[row * 68 + 4 * c4]);
            *reinterpret_cast<float4*>(out + ((size_t)(n0 + row) * BB + b) * HH + 4 * c4) = t;
        }
    }
}

// ---------------------------------------------------------------------------
extern "C" void kernel_launch(void* const* d_in, const int* in_sizes, int n_in,
                              void* d_out, int out_size)
{
    const float* q    = (const float*)d_in[0];
    const float* k    = (const float*)d_in[1];
    const float* v    = (const float*)d_in[2];
    const float* mask = (const float*)d_in[3];
    const float* Wq   = (const float*)d_in[4];
    const float* bq   = (const float*)d_in[5];
    const float* Wk   = (const float*)d_in[6];
    const float* bk   = (const float*)d_in[7];
    const float* Wv   = (const float*)d_in[8];
    const float* bv   = (const float*)d_in[9];

    float* out  = (float*)d_out;                         // [N,B,H] first
    float* Aout = (float*)d_out + (size_t)NN * BB * HH;  // then [B,N,N]

    const int smem_bytes = SMEM_FLOATS * 4;
    cudaFuncSetAttribute(attn_kernel, cudaFuncAttributeMaxDynamicSharedMemorySize,
                         smem_bytes);

    proj_kernel<<<dim3((NN * BB) / 128, 3), 256>>>(q, k, v, Wq, bq, Wk, bk, Wv, bv);
    attn_kernel<<<dim3(NN / 32, BB), 256, smem_bytes>>>(mask, out, Aout);
}